// round 14
// baseline (speedup 1.0000x reference)
#include <cuda_runtime.h>
#include <stdint.h>

#define NNODES      100000
#define NGRAPHS     128
#define HDIM        256
#define CHUNK_EDGES 2048          // 256 threads * 8 edges

// Scratch (no allocation allowed)
__device__ float d_agg[NNODES];
__device__ int   d_starts[NGRAPHS + 1];
__device__ int   d_chunk = 0;     // work-steal cursor; pool resets it to 0

// ---------------------------------------------------------------------------
// Kernel A: one-wave grid (1184 blocks).  Blocks [0,bndBlocks) first do
// boundary detection on the sorted batch array, then ALL blocks join a
// work-stealing loop over edge chunks (2048 edges each):
//     agg[dst] += x[src],  8 edges/thread, int4 index loads, REDs.
// Stealing removes the wave-quantization tail the static grid suffered.
// ---------------------------------------------------------------------------
__global__ __launch_bounds__(256)
void edge_boundary_kernel(const int* __restrict__ ei,
                          const float* __restrict__ x,
                          const int* __restrict__ batch,
                          int E, int N, int nChunks, int bndBlocks) {
    const int bid = (int)blockIdx.x;
    const int tid = threadIdx.x;

    if (bid < bndBlocks) {
        // ---- boundary detection, 4 nodes/thread ----
        int t    = bid * blockDim.x + tid;
        int base = t << 2;
        if (base < N) {
            int b0, b1, b2, b3;
            if (base + 3 < N) {
                int4 v = __ldg(reinterpret_cast<const int4*>(batch + base));
                b0 = v.x; b1 = v.y; b2 = v.z; b3 = v.w;
            } else {
                b0 = batch[base];
                b1 = (base + 1 < N) ? batch[base + 1] : b0;
                b2 = (base + 2 < N) ? batch[base + 2] : b1;
                b3 = (base + 3 < N) ? batch[base + 3] : b2;
            }
            int prev = (base == 0) ? -1 : __ldg(batch + base - 1);
            #pragma unroll
            for (int e = 0; e < 4; e++) {
                int idx = base + e;
                int b = (e == 0) ? b0 : (e == 1) ? b1 : (e == 2) ? b2 : b3;
                if (idx < N) {
                    for (int g = prev + 1; g <= b; g++) d_starts[g] = idx;
                    prev = b;
                    if (idx == N - 1)
                        for (int g = b + 1; g <= NGRAPHS; g++) d_starts[g] = N;
                }
            }
        }
    }

    // ---- work-stealing edge loop ----
    __shared__ int s_chunk;
    for (;;) {
        if (tid == 0) s_chunk = atomicAdd(&d_chunk, 1);
        __syncthreads();
        const int c = s_chunk;
        __syncthreads();          // all read s_chunk before next overwrite
        if (c >= nChunks) break;

        int i = c * CHUNK_EDGES + (tid << 3);
        if (i + 7 < E) {
            const int4* sp = reinterpret_cast<const int4*>(ei + i);
            const int4* dp = reinterpret_cast<const int4*>(ei + E + i);
            int4 s0 = __ldg(sp);
            int4 s1 = __ldg(sp + 1);
            int4 d0 = __ldg(dp);
            int4 d1 = __ldg(dp + 1);
            float v0 = __ldg(x + s0.x);
            float v1 = __ldg(x + s0.y);
            float v2 = __ldg(x + s0.z);
            float v3 = __ldg(x + s0.w);
            float v4 = __ldg(x + s1.x);
            float v5 = __ldg(x + s1.y);
            float v6 = __ldg(x + s1.z);
            float v7 = __ldg(x + s1.w);
            atomicAdd(&d_agg[d0.x], v0);
            atomicAdd(&d_agg[d0.y], v1);
            atomicAdd(&d_agg[d0.z], v2);
            atomicAdd(&d_agg[d0.w], v3);
            atomicAdd(&d_agg[d1.x], v4);
            atomicAdd(&d_agg[d1.y], v5);
            atomicAdd(&d_agg[d1.z], v6);
            atomicAdd(&d_agg[d1.w], v7);
        } else if (i < E) {
            int lim = min(i + 8, E);
            for (int e = i; e < lim; e++)
                atomicAdd(&d_agg[ei[E + e]], __ldg(x + ei[e]));
        }
    }
}

// ---------------------------------------------------------------------------
// Kernel B (PDL secondary, no trigger — proven launch path): one block per
// graph.  Weight-only prologue; grid-dependency sync; then the agg scan.
// Block 0 also resets the work-steal cursor for the next launch.
// ---------------------------------------------------------------------------
__global__ __launch_bounds__(HDIM)
void pool_kernel(const float* __restrict__ W_l,
                 const float* __restrict__ b_l,
                 const float* __restrict__ W_out,
                 const float* __restrict__ b_out,
                 float* __restrict__ out) {
    const int g = blockIdx.x;
    const int t = threadIdx.x;
    const int wid = t >> 5, lid = t & 31;

    // ---- prologue: weight-only constants ----
    const float w  = W_l[t];
    const float b  = b_l[t];
    const float wo = W_out[t];
    const float bo = b_out[0];
    const int allz = __syncthreads_and(b == 0.0f);
    float p = (w > 0.0f) ? wo * w : 0.0f;
    float n = (w < 0.0f) ? wo * w : 0.0f;
    #pragma unroll
    for (int off = 16; off; off >>= 1) {
        p += __shfl_xor_sync(0xffffffffu, p, off);
        n += __shfl_xor_sync(0xffffffffu, n, off);
    }
    __shared__ float sp8[8], sn8[8];
    if (lid == 0) { sp8[wid] = p; sn8[wid] = n; }
    __syncthreads();
    float P = 0.0f, Nn = 0.0f;
    #pragma unroll
    for (int wI = 0; wI < 8; wI++) { P += sp8[wI]; Nn += sn8[wI]; }

    // ---- wait for kernel A (no-op outside PDL) ----
#if __CUDA_ARCH__ >= 900
    cudaGridDependencySynchronize();
#endif

    // reset the steal cursor for the next launch (edge kernel is done with it)
    if (g == 0 && t == 0) d_chunk = 0;

    const int start = d_starts[g];
    const int end   = d_starts[g + 1];
    const int len   = end - start;
    const float cnt = fmaxf((float)len, 1.0f);

    __shared__ float red0[8], red1[8];

    if (allz) {
        // fast path: Sum_k wo_k*relu(v*w_k) == P*max(v,0) + Nn*min(v,0)
        float sp = 0.0f, sn = 0.0f;
        const int a0 = min((start + 3) & ~3, end);   // first 16B-aligned idx
        const int a1 = max(end & ~3, a0);            // end of aligned region
        if (t < 4) {                                  // head peel (<=3)
            int hh = start + t;
            if (hh < a0) {
                float v = d_agg[hh];
                sp += fmaxf(v, 0.0f);
                sn += fminf(v, 0.0f);
            }
        } else if (t < 8) {                           // tail peel (<=3)
            int ti = a1 + (t - 4);
            if (ti < end) {
                float v = d_agg[ti];
                sp += fmaxf(v, 0.0f);
                sn += fminf(v, 0.0f);
            }
        }
        if (a1 > a0) {
            const float4* va = reinterpret_cast<const float4*>(d_agg + a0);
            const int nv = (a1 - a0) >> 2;
            for (int i = t; i < nv; i += HDIM) {
                float4 v = va[i];
                sp += fmaxf(v.x, 0.0f) + fmaxf(v.y, 0.0f)
                    + fmaxf(v.z, 0.0f) + fmaxf(v.w, 0.0f);
                sn += fminf(v.x, 0.0f) + fminf(v.y, 0.0f)
                    + fminf(v.z, 0.0f) + fminf(v.w, 0.0f);
            }
        }
        #pragma unroll
        for (int off = 16; off; off >>= 1) {
            sp += __shfl_xor_sync(0xffffffffu, sp, off);
            sn += __shfl_xor_sync(0xffffffffu, sn, off);
        }
        if (lid == 0) { red0[wid] = sp; red1[wid] = sn; }
        __syncthreads();
        if (t == 0) {
            float SP = 0.0f, SN = 0.0f;
            #pragma unroll
            for (int wI = 0; wI < 8; wI++) { SP += red0[wI]; SN += red1[wI]; }
            out[g] = fmaxf((P * SP + Nn * SN) / cnt + bo, 0.0f);
        }
        return;
    }

    // exact slow path (general b_l): one thread per feature
    float acc = 0.0f;
    __shared__ float sa[HDIM];
    for (int base = start; base < end; base += HDIM) {
        int nn = min(HDIM, end - base);
        __syncthreads();
        if (t < nn) sa[t] = d_agg[base + t];
        __syncthreads();
        float q0 = 0.f, q1 = 0.f, q2 = 0.f, q3 = 0.f;
        int j = 0;
        for (; j + 3 < nn; j += 4) {
            q0 += fmaxf(fmaf(sa[j],     w, b), 0.0f);
            q1 += fmaxf(fmaf(sa[j + 1], w, b), 0.0f);
            q2 += fmaxf(fmaf(sa[j + 2], w, b), 0.0f);
            q3 += fmaxf(fmaf(sa[j + 3], w, b), 0.0f);
        }
        for (; j < nn; j++)
            q0 += fmaxf(fmaf(sa[j], w, b), 0.0f);
        acc += (q0 + q1) + (q2 + q3);
    }
    float val = acc * wo / cnt;
    #pragma unroll
    for (int off = 16; off; off >>= 1)
        val += __shfl_xor_sync(0xffffffffu, val, off);
    if (lid == 0) red0[wid] = val;
    __syncthreads();
    if (t == 0) {
        float v = 0.0f;
        #pragma unroll
        for (int wI = 0; wI < 8; wI++) v += red0[wI];
        out[g] = fmaxf(v + bo, 0.0f);
    }
}

// ---------------------------------------------------------------------------
// inputs (metadata order):
//   0: x float32[N]  1: ei int32[2E]  2: batch int32[N]
//   3: W_l f32[256]  4: b_l f32[256]  5: W_out f32[256]  6: b_out f32[1]
// out: float32 [128]
// ---------------------------------------------------------------------------
extern "C" void kernel_launch(void* const* d_in, const int* in_sizes, int n_in,
                              void* d_out, int out_size) {
    const float* x     = (const float*)d_in[0];
    const int*   ei    = (const int*)d_in[1];
    const int*   batch = (const int*)d_in[2];
    const float* W_l   = (const float*)d_in[3];
    const float* b_l   = (const float*)d_in[4];
    const float* W_out = (const float*)d_in[5];
    const float* b_out = (const float*)d_in[6];
    float*       out   = (float*)d_out;

    const int N = in_sizes[0];
    const int E = in_sizes[1] / 2;

    // zero agg via memset node
    void* aggp = nullptr;
    cudaGetSymbolAddress(&aggp, d_agg);
    cudaMemsetAsync(aggp, 0, (size_t)N * sizeof(float), 0);

    const int threads   = 256;
    const int nChunks   = (E + CHUNK_EDGES - 1) / CHUNK_EDGES;
    const int bndBlocks = ((N + 3) / 4 + threads - 1) / threads;
    const int oneWave   = 148 * 8;                       // 1184 resident slots
    const int grid      = oneWave;

    edge_boundary_kernel<<<grid, threads>>>(ei, x, batch, E, N, nChunks, bndBlocks);

    // Pool via the proven PDL launch path (no trigger); fall back to a plain
    // launch on any failure.
    cudaError_t lerr = cudaErrorUnknown;
    {
        cudaLaunchConfig_t cfg = {};
        cfg.gridDim  = dim3(NGRAPHS, 1, 1);
        cfg.blockDim = dim3(HDIM, 1, 1);
        cfg.dynamicSmemBytes = 0;
        cfg.stream = 0;
        cudaLaunchAttribute attrs[1];
        attrs[0].id = cudaLaunchAttributeProgrammaticStreamSerialization;
        attrs[0].val.programmaticStreamSerializationAllowed = 1;
        cfg.attrs = attrs;
        cfg.numAttrs = 1;
        lerr = cudaLaunchKernelEx(&cfg, pool_kernel, W_l, b_l, W_out, b_out, out);
    }
    if (lerr != cudaSuccess) {
        (void)cudaGetLastError();
        pool_kernel<<<NGRAPHS, HDIM>>>(W_l, b_l, W_out, b_out, out);
    }
}

// round 16
// speedup vs baseline: 1.2742x; 1.2742x over previous
#include <cuda_runtime.h>
#include <stdint.h>

#define NNODES      100000
#define NGRAPHS     128
#define HDIM        256
#define CHUNK_EDGES 2048          // 256 threads * 8 edges
#define EDGE_BLOCKS 1184          // one full wave: 148 SMs * 8 blocks

// Scratch (no allocation allowed)
__device__ float d_agg[NNODES];
__device__ int   d_starts[NGRAPHS + 1];

// ---------------------------------------------------------------------------
// Kernel A: blocks [0, bndBlocks) do boundary detection (short; slots
// backfill), blocks [bndBlocks, +EDGE_BLOCKS) run the edge scatter with a
// DETERMINISTIC chunk-stride loop (no atomics, no barriers): edge block j
// processes chunks j, j+EDGE_BLOCKS, ...  Inner loop identical to the proven
// R8 kernel: 8 edges/thread, front-batched int4 index loads, REDs.
// ---------------------------------------------------------------------------
__global__ __launch_bounds__(256)
void edge_boundary_kernel(const int* __restrict__ ei,
                          const float* __restrict__ x,
                          const int* __restrict__ batch,
                          int E, int N, int nChunks, int bndBlocks) {
    const int bid = (int)blockIdx.x;
    const int tid = threadIdx.x;

    if (bid < bndBlocks) {
        // ---- boundary detection on sorted batch, 4 nodes/thread ----
        int t    = bid * blockDim.x + tid;
        int base = t << 2;
        if (base >= N) return;
        int b0, b1, b2, b3;
        if (base + 3 < N) {
            int4 v = __ldg(reinterpret_cast<const int4*>(batch + base));
            b0 = v.x; b1 = v.y; b2 = v.z; b3 = v.w;
        } else {
            b0 = batch[base];
            b1 = (base + 1 < N) ? batch[base + 1] : b0;
            b2 = (base + 2 < N) ? batch[base + 2] : b1;
            b3 = (base + 3 < N) ? batch[base + 3] : b2;
        }
        int prev = (base == 0) ? -1 : __ldg(batch + base - 1);
        #pragma unroll
        for (int e = 0; e < 4; e++) {
            int idx = base + e;
            int b = (e == 0) ? b0 : (e == 1) ? b1 : (e == 2) ? b2 : b3;
            if (idx < N) {
                for (int g = prev + 1; g <= b; g++) d_starts[g] = idx;
                prev = b;
                if (idx == N - 1)
                    for (int g = b + 1; g <= NGRAPHS; g++) d_starts[g] = N;
            }
        }
        return;
    }

    // ---- edge scatter: chunk-stride loop, no synchronization ----
    const int j = bid - bndBlocks;               // edge block id 0..EDGE_BLOCKS-1
    for (int c = j; c < nChunks; c += EDGE_BLOCKS) {
        int i = c * CHUNK_EDGES + (tid << 3);
        if (i + 7 < E) {
            const int4* sp = reinterpret_cast<const int4*>(ei + i);
            const int4* dp = reinterpret_cast<const int4*>(ei + E + i);
            int4 s0 = __ldg(sp);
            int4 s1 = __ldg(sp + 1);
            int4 d0 = __ldg(dp);
            int4 d1 = __ldg(dp + 1);
            float v0 = __ldg(x + s0.x);
            float v1 = __ldg(x + s0.y);
            float v2 = __ldg(x + s0.z);
            float v3 = __ldg(x + s0.w);
            float v4 = __ldg(x + s1.x);
            float v5 = __ldg(x + s1.y);
            float v6 = __ldg(x + s1.z);
            float v7 = __ldg(x + s1.w);
            atomicAdd(&d_agg[d0.x], v0);
            atomicAdd(&d_agg[d0.y], v1);
            atomicAdd(&d_agg[d0.z], v2);
            atomicAdd(&d_agg[d0.w], v3);
            atomicAdd(&d_agg[d1.x], v4);
            atomicAdd(&d_agg[d1.y], v5);
            atomicAdd(&d_agg[d1.z], v6);
            atomicAdd(&d_agg[d1.w], v7);
        } else if (i < E) {
            int lim = min(i + 8, E);
            for (int e = i; e < lim; e++)
                atomicAdd(&d_agg[ei[E + e]], __ldg(x + ei[e]));
        }
    }
}

// ---------------------------------------------------------------------------
// Kernel B (PDL secondary, no trigger — proven launch path): one block per
// graph.  Weight-only prologue; grid-dependency sync; then the agg scan.
// ---------------------------------------------------------------------------
__global__ __launch_bounds__(HDIM)
void pool_kernel(const float* __restrict__ W_l,
                 const float* __restrict__ b_l,
                 const float* __restrict__ W_out,
                 const float* __restrict__ b_out,
                 float* __restrict__ out) {
    const int g = blockIdx.x;
    const int t = threadIdx.x;
    const int wid = t >> 5, lid = t & 31;

    // ---- prologue: weight-only constants ----
    const float w  = W_l[t];
    const float b  = b_l[t];
    const float wo = W_out[t];
    const float bo = b_out[0];
    const int allz = __syncthreads_and(b == 0.0f);
    float p = (w > 0.0f) ? wo * w : 0.0f;
    float n = (w < 0.0f) ? wo * w : 0.0f;
    #pragma unroll
    for (int off = 16; off; off >>= 1) {
        p += __shfl_xor_sync(0xffffffffu, p, off);
        n += __shfl_xor_sync(0xffffffffu, n, off);
    }
    __shared__ float sp8[8], sn8[8];
    if (lid == 0) { sp8[wid] = p; sn8[wid] = n; }
    __syncthreads();
    float P = 0.0f, Nn = 0.0f;
    #pragma unroll
    for (int wI = 0; wI < 8; wI++) { P += sp8[wI]; Nn += sn8[wI]; }

    // ---- wait for kernel A (no-op outside PDL) ----
#if __CUDA_ARCH__ >= 900
    cudaGridDependencySynchronize();
#endif

    const int start = d_starts[g];
    const int end   = d_starts[g + 1];
    const int len   = end - start;
    const float cnt = fmaxf((float)len, 1.0f);

    __shared__ float red0[8], red1[8];

    if (allz) {
        // fast path: Sum_k wo_k*relu(v*w_k) == P*max(v,0) + Nn*min(v,0)
        float sp = 0.0f, sn = 0.0f;
        const int a0 = min((start + 3) & ~3, end);   // first 16B-aligned idx
        const int a1 = max(end & ~3, a0);            // end of aligned region
        if (t < 4) {                                  // head peel (<=3)
            int hh = start + t;
            if (hh < a0) {
                float v = d_agg[hh];
                sp += fmaxf(v, 0.0f);
                sn += fminf(v, 0.0f);
            }
        } else if (t < 8) {                           // tail peel (<=3)
            int ti = a1 + (t - 4);
            if (ti < end) {
                float v = d_agg[ti];
                sp += fmaxf(v, 0.0f);
                sn += fminf(v, 0.0f);
            }
        }
        if (a1 > a0) {
            const float4* va = reinterpret_cast<const float4*>(d_agg + a0);
            const int nv = (a1 - a0) >> 2;
            for (int i = t; i < nv; i += HDIM) {
                float4 v = va[i];
                sp += fmaxf(v.x, 0.0f) + fmaxf(v.y, 0.0f)
                    + fmaxf(v.z, 0.0f) + fmaxf(v.w, 0.0f);
                sn += fminf(v.x, 0.0f) + fminf(v.y, 0.0f)
                    + fminf(v.z, 0.0f) + fminf(v.w, 0.0f);
            }
        }
        #pragma unroll
        for (int off = 16; off; off >>= 1) {
            sp += __shfl_xor_sync(0xffffffffu, sp, off);
            sn += __shfl_xor_sync(0xffffffffu, sn, off);
        }
        if (lid == 0) { red0[wid] = sp; red1[wid] = sn; }
        __syncthreads();
        if (t == 0) {
            float SP = 0.0f, SN = 0.0f;
            #pragma unroll
            for (int wI = 0; wI < 8; wI++) { SP += red0[wI]; SN += red1[wI]; }
            out[g] = fmaxf((P * SP + Nn * SN) / cnt + bo, 0.0f);
        }
        return;
    }

    // exact slow path (general b_l): one thread per feature
    float acc = 0.0f;
    __shared__ float sa[HDIM];
    for (int base = start; base < end; base += HDIM) {
        int nn = min(HDIM, end - base);
        __syncthreads();
        if (t < nn) sa[t] = d_agg[base + t];
        __syncthreads();
        float q0 = 0.f, q1 = 0.f, q2 = 0.f, q3 = 0.f;
        int j = 0;
        for (; j + 3 < nn; j += 4) {
            q0 += fmaxf(fmaf(sa[j],     w, b), 0.0f);
            q1 += fmaxf(fmaf(sa[j + 1], w, b), 0.0f);
            q2 += fmaxf(fmaf(sa[j + 2], w, b), 0.0f);
            q3 += fmaxf(fmaf(sa[j + 3], w, b), 0.0f);
        }
        for (; j < nn; j++)
            q0 += fmaxf(fmaf(sa[j], w, b), 0.0f);
        acc += (q0 + q1) + (q2 + q3);
    }
    float val = acc * wo / cnt;
    #pragma unroll
    for (int off = 16; off; off >>= 1)
        val += __shfl_xor_sync(0xffffffffu, val, off);
    if (lid == 0) red0[wid] = val;
    __syncthreads();
    if (t == 0) {
        float v = 0.0f;
        #pragma unroll
        for (int wI = 0; wI < 8; wI++) v += red0[wI];
        out[g] = fmaxf(v + bo, 0.0f);
    }
}

// ---------------------------------------------------------------------------
// inputs (metadata order):
//   0: x float32[N]  1: ei int32[2E]  2: batch int32[N]
//   3: W_l f32[256]  4: b_l f32[256]  5: W_out f32[256]  6: b_out f32[1]
// out: float32 [128]
// ---------------------------------------------------------------------------
extern "C" void kernel_launch(void* const* d_in, const int* in_sizes, int n_in,
                              void* d_out, int out_size) {
    const float* x     = (const float*)d_in[0];
    const int*   ei    = (const int*)d_in[1];
    const int*   batch = (const int*)d_in[2];
    const float* W_l   = (const float*)d_in[3];
    const float* b_l   = (const float*)d_in[4];
    const float* W_out = (const float*)d_in[5];
    const float* b_out = (const float*)d_in[6];
    float*       out   = (float*)d_out;

    const int N = in_sizes[0];
    const int E = in_sizes[1] / 2;

    // zero agg via memset node
    void* aggp = nullptr;
    cudaGetSymbolAddress(&aggp, d_agg);
    cudaMemsetAsync(aggp, 0, (size_t)N * sizeof(float), 0);

    const int threads   = 256;
    const int nChunks   = (E + CHUNK_EDGES - 1) / CHUNK_EDGES;
    const int bndBlocks = ((N + 3) / 4 + threads - 1) / threads;
    const int grid      = bndBlocks + EDGE_BLOCKS;

    edge_boundary_kernel<<<grid, threads>>>(ei, x, batch, E, N, nChunks, bndBlocks);

    // Pool via the proven PDL launch path (no trigger); fall back to a plain
    // launch on any failure.
    cudaError_t lerr = cudaErrorUnknown;
    {
        cudaLaunchConfig_t cfg = {};
        cfg.gridDim  = dim3(NGRAPHS, 1, 1);
        cfg.blockDim = dim3(HDIM, 1, 1);
        cfg.dynamicSmemBytes = 0;
        cfg.stream = 0;
        cudaLaunchAttribute attrs[1];
        attrs[0].id = cudaLaunchAttributeProgrammaticStreamSerialization;
        attrs[0].val.programmaticStreamSerializationAllowed = 1;
        cfg.attrs = attrs;
        cfg.numAttrs = 1;
        lerr = cudaLaunchKernelEx(&cfg, pool_kernel, W_l, b_l, W_out, b_out, out);
    }
    if (lerr != cudaSuccess) {
        (void)cudaGetLastError();
        pool_kernel<<<NGRAPHS, HDIM>>>(W_l, b_l, W_out, b_out, out);
    }
}